// round 9
// baseline (speedup 1.0000x reference)
#include <cuda_runtime.h>
#include <cuda_fp16.h>
#include <stdint.h>

#define NPTS    1048576
#define NTILES  8192
#define THREADS 384
#define XSTRIDE 368
#define WSTRIDE 136
#define OFF_W0 0
#define OFF_W1 47872
#define OFF_W2 82688
#define OFF_W3 117504
#define OFF_W4 152320
#define OFF_B  154368
#define OFF_B4 156416
#define OFF_X  156448
#define SMEM_TOTAL 203552

__device__ __forceinline__ uint32_t s2u(const void* p) {
    uint32_t a;
    asm("{ .reg .u64 t; cvta.to.shared.u64 t, %1; cvt.u32.u64 %0, t; }" : "=r"(a) : "l"(p));
    return a;
}
__device__ __forceinline__ uint32_t packh2(float lo, float hi) {
    uint32_t r;
    asm("cvt.rn.f16x2.f32 %0, %1, %2;" : "=r"(r) : "f"(hi), "f"(lo));
    return r;
}
#define LDSM_X4(R, a) asm volatile("ldmatrix.sync.aligned.m8n8.x4.shared.b16 {%0,%1,%2,%3}, [%4];" \
    : "=r"((R)[0]), "=r"((R)[1]), "=r"((R)[2]), "=r"((R)[3]) : "r"(a))
#define LDSM_X4_T(R, a) asm volatile("ldmatrix.sync.aligned.m8n8.x4.trans.shared.b16 {%0,%1,%2,%3}, [%4];" \
    : "=r"((R)[0]), "=r"((R)[1]), "=r"((R)[2]), "=r"((R)[3]) : "r"(a))
#define LDSM_X2_T(R, a) asm volatile("ldmatrix.sync.aligned.m8n8.x2.trans.shared.b16 {%0,%1}, [%2];" \
    : "=r"((R)[0]), "=r"((R)[1]) : "r"(a))
#define MMA(C, A, B0, B1) asm volatile("mma.sync.aligned.m16n8k16.row.col.f32.f16.f16.f32 " \
    "{%0,%1,%2,%3}, {%4,%5,%6,%7}, {%8,%9}, {%0,%1,%2,%3};" \
    : "+f"((C)[0]), "+f"((C)[1]), "+f"((C)[2]), "+f"((C)[3]) \
    : "r"((A)[0]), "r"((A)[1]), "r"((A)[2]), "r"((A)[3]), "r"(B0), "r"(B1))
#define BSYNC(id)   asm volatile("bar.sync %0, %1;"   :: "r"(id), "r"(THREADS) : "memory")
#define BARRIVE(id) asm volatile("bar.arrive %0, %1;" :: "r"(id), "r"(THREADS) : "memory")

// fast-math-proof sincos: double range reduction + fdlibm float polys
__device__ __forceinline__ void sincos_pos(float x, float& s, float& c) {
    float nf = rintf(x * 0.63661977236758134f);
    float rf = (float)((double)x - (double)nf * 1.5707963267948966);
    int q = (int)nf;
    float r2 = rf * rf;
    float ps = fmaf(r2, 2.7557314297e-06f, -1.9841271110e-04f);
    ps = fmaf(r2, ps, 8.3333337680e-03f);
    ps = fmaf(r2, ps, -1.6666667163e-01f);
    float sr = fmaf(rf * r2, ps, rf);
    float pc = fmaf(r2, 2.4760174663e-05f, -1.3888889225e-03f);
    pc = fmaf(r2, pc, 4.1666667908e-02f);
    pc = fmaf(r2, pc, -0.5f);
    float cr = fmaf(r2, pc, 1.0f);
    if (q & 1) { float t = sr; sr = cr; cr = -t; }
    if (q & 2) { sr = -sr; cr = -cr; }
    s = sr; c = cr;
}

__device__ __forceinline__ void relu_pack(float acc[16][4], uint32_t a[8][4]) {
#pragma unroll
    for (int n = 0; n < 16; ++n)
#pragma unroll
        for (int j = 0; j < 4; ++j) { float v = acc[n][j]; acc[n][j] = fmaxf(v, 0.01f * v); }
#pragma unroll
    for (int j = 0; j < 8; ++j) {
        a[j][0] = packh2(acc[2*j][0],   acc[2*j][1]);
        a[j][1] = packh2(acc[2*j][2],   acc[2*j][3]);
        a[j][2] = packh2(acc[2*j+1][0], acc[2*j+1][1]);
        a[j][3] = packh2(acc[2*j+1][2], acc[2*j+1][3]);
    }
}

__device__ __forceinline__ void layer_hidden(uint32_t wl, const float* bl, int lane, uint32_t a[8][4]) {
    float acc[16][4];
    const int c0 = 2 * (lane & 3);
#pragma unroll
    for (int n = 0; n < 16; ++n) {
        float2 bv = *(const float2*)(bl + n * 8 + c0);
        acc[n][0] = bv.x; acc[n][1] = bv.y; acc[n][2] = bv.x; acc[n][3] = bv.y;
    }
#pragma unroll
    for (int k = 0; k < 8; ++k)
#pragma unroll
        for (int n2 = 0; n2 < 8; ++n2) {
            uint32_t B[4];
            LDSM_X4_T(B, wl + (uint32_t)(k * 16 * WSTRIDE + n2 * 16) * 2u);
            MMA(acc[2*n2],   a[k], B[0], B[1]);
            MMA(acc[2*n2+1], a[k], B[2], B[3]);
        }
    relu_pack(acc, a);
}

__global__ void __launch_bounds__(THREADS, 1)
fused_mlp(const float* __restrict__ UV, const float* __restrict__ FG,
          const float* __restrict__ W0, const float* __restrict__ b0,
          const float* __restrict__ W1, const float* __restrict__ b1,
          const float* __restrict__ W2, const float* __restrict__ b2,
          const float* __restrict__ W3, const float* __restrict__ b3,
          const float* __restrict__ W4, const float* __restrict__ b4,
          float* __restrict__ out)
{
    extern __shared__ char sm[];
    __half* sW0 = (__half*)(sm + OFF_W0);
    float*  sB  = (float*)(sm + OFF_B);
    float*  sB4 = (float*)(sm + OFF_B4);
    char*   sX  = sm + OFF_X;
    const int tid = threadIdx.x, lane = tid & 31, wid = tid >> 5;

    // one-time staging: W0 rows permuted (0-99: feat rows 66-165; 104-169: posenc rows 0-65)
    for (int i = tid; i < 176 * 128; i += THREADS) {
        int k = i >> 7, n = i & 127;
        float v = 0.0f;
        if (k < 100) v = W0[(66 + k) * 128 + n];
        else if (k >= 104 && k < 170) v = W0[(k - 104) * 128 + n];
        sW0[k * WSTRIDE + n] = __float2half_rn(v);
    }
    for (int i = tid; i < 128 * 128; i += THREADS) {
        int k = i >> 7, n = i & 127;
        ((__half*)(sm + OFF_W1))[k * WSTRIDE + n] = __float2half_rn(W1[i]);
        ((__half*)(sm + OFF_W2))[k * WSTRIDE + n] = __float2half_rn(W2[i]);
        ((__half*)(sm + OFF_W3))[k * WSTRIDE + n] = __float2half_rn(W3[i]);
    }
    for (int i = tid; i < 128 * 8; i += THREADS)
        ((__half*)(sm + OFF_W4))[i] = __float2half_rn((i & 7) < 3 ? W4[(i >> 3) * 3 + (i & 7)] : 0.0f);
    for (int i = tid; i < 128; i += THREADS) {
        sB[i] = b0[i]; sB[128 + i] = b1[i]; sB[256 + i] = b2[i]; sB[384 + i] = b3[i];
    }
    if (tid < 8) sB4[tid] = (tid < 3) ? b4[tid] : 0.0f;
    for (int i = tid; i < 128 * XSTRIDE / 4; i += THREADS) ((uint32_t*)sX)[i] = 0u;
    __syncthreads();

    const uint32_t wlp = (uint32_t)((lane & 15) * WSTRIDE + ((lane >> 4) << 3)) * 2u;

    if (wid >= 8) {  // ---------- producers: gather + posenc ----------
        const int row_base = (wid - 8) * 32;
        const float2* UV2 = (const float2*)UV;
        const float4* FG4 = (const float4*)FG;
        bool first = true;
        for (int t = blockIdx.x; t < NTILES; t += gridDim.x) {
            if (!first) BSYNC(2);
            first = false;
            const int myrow = row_base + lane;
            float2 uvp = UV2[t * 128 + myrow];
            float iU = 511.0f * uvp.x, iV = 511.0f * uvp.y;
            int iu0 = (int)floorf(iU), iu1 = (int)ceilf(iU);
            int iv0 = (int)floorf(iV), iv1 = (int)ceilf(iV);
            float fu = iU - (float)iu0, fv = iV - (float)iv0;
            int b00 = (iu0 * 512 + iv0) * 25, b10 = (iu1 * 512 + iv0) * 25;
            int b01 = (iu0 * 512 + iv1) * 25, b11 = (iu1 * 512 + iv1) * 25;
            float w00 = (1.f - fu) * (1.f - fv), w10 = fu * (1.f - fv);
            float w01 = (1.f - fu) * fv, w11 = fu * fv;
            float4 q[4][4];
#pragma unroll
            for (int s = 0; s < 4; ++s) {
                int c00 = __shfl_sync(~0u, b00, s), c10 = __shfl_sync(~0u, b10, s);
                int c01 = __shfl_sync(~0u, b01, s), c11 = __shfl_sync(~0u, b11, s);
                if (lane < 25) {
                    q[s][0] = FG4[c00 + lane]; q[s][1] = FG4[c10 + lane];
                    q[s][2] = FG4[c01 + lane]; q[s][3] = FG4[c11 + lane];
                }
            }
#pragma unroll 4
            for (int p = 0; p < 32; ++p) {
                const int s = p & 3;
                float u00 = __shfl_sync(~0u, w00, p), u10 = __shfl_sync(~0u, w10, p);
                float u01 = __shfl_sync(~0u, w01, p), u11 = __shfl_sync(~0u, w11, p);
                if (lane < 25) {
                    float4 f;
                    f.x = q[s][0].x*u00 + q[s][1].x*u10 + q[s][2].x*u01 + q[s][3].x*u11;
                    f.y = q[s][0].y*u00 + q[s][1].y*u10 + q[s][2].y*u01 + q[s][3].y*u11;
                    f.z = q[s][0].z*u00 + q[s][1].z*u10 + q[s][2].z*u01 + q[s][3].z*u11;
                    f.w = q[s][0].w*u00 + q[s][1].w*u10 + q[s][2].w*u01 + q[s][3].w*u11;
                    uint2 st; st.x = packh2(f.x, f.y); st.y = packh2(f.z, f.w);
                    *(uint2*)(sX + (row_base + p) * XSTRIDE + lane * 8) = st;
                }
                const int np = p + 4;
                if (np < 32) {
                    int c00 = __shfl_sync(~0u, b00, np), c10 = __shfl_sync(~0u, b10, np);
                    int c01 = __shfl_sync(~0u, b01, np), c11 = __shfl_sync(~0u, b11, np);
                    if (lane < 25) {
                        q[s][0] = FG4[c00 + lane]; q[s][1] = FG4[c10 + lane];
                        q[s][2] = FG4[c01 + lane]; q[s][3] = FG4[c11 + lane];
                    }
                }
            }
            {   // posenc: cols 104..169 (order U,V, sU,sV, cU,cV, ...)
                char* dst = sX + myrow * XSTRIDE + 208;
                *(uint32_t*)dst = packh2(uvp.x, uvp.y);
                float kf = 1.0f;
                for (int i = 0; i < 16; ++i) {
                    float su, cu, sv, cv;
                    sincos_pos(kf * uvp.x, su, cu);
                    sincos_pos(kf * uvp.y, sv, cv);
                    *(uint32_t*)(dst + 4 + 8 * i) = packh2(su, sv);
                    *(uint32_t*)(dst + 8 + 8 * i) = packh2(cu, cv);
                    kf *= 2.0f;
                }
            }
            asm volatile("membar.cta;" ::: "memory");
            BARRIVE(1);
        }
    } else {  // ---------- consumers: 5-layer MLP, register-chained ----------
        const int m0 = wid * 16;
        const uint32_t xs = s2u(sX) + (uint32_t)((m0 + (lane & 15)) * XSTRIDE + ((lane >> 4) << 4));
        const int c0 = 2 * (lane & 3);
        for (int t = blockIdx.x; t < NTILES; t += gridDim.x) {
            BSYNC(1);
            uint32_t a0[11][4];
#pragma unroll
            for (int k = 0; k < 11; ++k) LDSM_X4(a0[k], xs + (uint32_t)(k * 32));
            float acc[16][4];
#pragma unroll
            for (int n = 0; n < 16; ++n) {
                float2 bv = *(const float2*)(sB + n * 8 + c0);
                acc[n][0] = bv.x; acc[n][1] = bv.y; acc[n][2] = bv.x; acc[n][3] = bv.y;
            }
            const uint32_t w0l = s2u(sm + OFF_W0) + wlp;
#pragma unroll
            for (int k = 0; k < 11; ++k)
#pragma unroll
                for (int n2 = 0; n2 < 8; ++n2) {
                    uint32_t B[4];
                    LDSM_X4_T(B, w0l + (uint32_t)(k * 16 * WSTRIDE + n2 * 16) * 2u);
                    MMA(acc[2*n2],   a0[k], B[0], B[1]);
                    MMA(acc[2*n2+1], a0[k], B[2], B[3]);
                }
            BARRIVE(2);  // X consumed -> producers refill
            uint32_t a[8][4];
            relu_pack(acc, a);
            layer_hidden(s2u(sm + OFF_W1) + wlp, sB + 128, lane, a);
            layer_hidden(s2u(sm + OFF_W2) + wlp, sB + 256, lane, a);
            layer_hidden(s2u(sm + OFF_W3) + wlp, sB + 384, lane, a);
            float c4[4];
            c4[0] = sB4[c0]; c4[1] = sB4[c0 + 1]; c4[2] = c4[0]; c4[3] = c4[1];
            const uint32_t w4l = s2u(sm + OFF_W4) + (uint32_t)((lane & 15) * 16);
#pragma unroll
            for (int k = 0; k < 8; ++k) {
                uint32_t B[2];
                LDSM_X2_T(B, w4l + (uint32_t)(k * 256));
                MMA(c4, a[k], B[0], B[1]);
            }
            const int pt = t * 128 + m0 + (lane >> 2);
            if ((lane & 3) == 0) {
                out[pt * 3 + 0] = c4[0];       out[pt * 3 + 1] = c4[1];
                out[(pt + 8) * 3 + 0] = c4[2]; out[(pt + 8) * 3 + 1] = c4[3];
            } else if ((lane & 3) == 1) {
                out[pt * 3 + 2] = c4[0];
                out[(pt + 8) * 3 + 2] = c4[2];
            }
        }
    }
}

extern "C" void kernel_launch(void* const* d_in, const int* in_sizes, int n_in,
                              void* d_out, int out_size) {
    int dev = 0, sms = 148;
    cudaGetDevice(&dev);
    cudaDeviceGetAttribute(&sms, cudaDevAttrMultiProcessorCount, dev);
    if (sms <= 0) sms = 148;
    if (sms > NTILES) sms = NTILES;
    cudaFuncSetAttribute(fused_mlp, cudaFuncAttributeMaxDynamicSharedMemorySize, SMEM_TOTAL);
    fused_mlp<<<sms, THREADS, SMEM_TOTAL>>>(
        (const float*)d_in[0], (const float*)d_in[1],
        (const float*)d_in[2], (const float*)d_in[3],
        (const float*)d_in[4], (const float*)d_in[5],
        (const float*)d_in[6], (const float*)d_in[7],
        (const float*)d_in[8], (const float*)d_in[9],
        (const float*)d_in[10], (const float*)d_in[11],
        (float*)d_out);
}

// round 10
// speedup vs baseline: 1.0020x; 1.0020x over previous
#include <cuda_runtime.h>
#include <cuda_fp16.h>
#include <stdint.h>

#define NPTS    1048576
#define NTILES  8192
#define THREADS 384
#define XSTRIDE 368
#define WSTRIDE 136
#define OFF_W0 0
#define OFF_W1 47872
#define OFF_W2 82688
#define OFF_W3 117504
#define OFF_W4 152320
#define OFF_B  154368
#define OFF_B4 156416
#define OFF_X  156448
#define SMEM_TOTAL 203552

__device__ __forceinline__ uint32_t s2u(const void* p) {
    uint32_t a;
    asm("{ .reg .u64 t; cvta.to.shared.u64 t, %1; cvt.u32.u64 %0, t; }" : "=r"(a) : "l"(p));
    return a;
}
__device__ __forceinline__ uint32_t packh2(float lo, float hi) {
    uint32_t r;
    asm("cvt.rn.f16x2.f32 %0, %1, %2;" : "=r"(r) : "f"(hi), "f"(lo));
    return r;
}
#define LDSM_X4(R, a) asm volatile("ldmatrix.sync.aligned.m8n8.x4.shared.b16 {%0,%1,%2,%3}, [%4];" \
    : "=r"((R)[0]), "=r"((R)[1]), "=r"((R)[2]), "=r"((R)[3]) : "r"(a))
#define LDSM_X4_T(R, a) asm volatile("ldmatrix.sync.aligned.m8n8.x4.trans.shared.b16 {%0,%1,%2,%3}, [%4];" \
    : "=r"((R)[0]), "=r"((R)[1]), "=r"((R)[2]), "=r"((R)[3]) : "r"(a))
#define LDSM_X2_T(R, a) asm volatile("ldmatrix.sync.aligned.m8n8.x2.trans.shared.b16 {%0,%1}, [%2];" \
    : "=r"((R)[0]), "=r"((R)[1]) : "r"(a))
#define MMA(C, A, B0, B1) asm volatile("mma.sync.aligned.m16n8k16.row.col.f32.f16.f16.f32 " \
    "{%0,%1,%2,%3}, {%4,%5,%6,%7}, {%8,%9}, {%0,%1,%2,%3};" \
    : "+f"((C)[0]), "+f"((C)[1]), "+f"((C)[2]), "+f"((C)[3]) \
    : "r"((A)[0]), "r"((A)[1]), "r"((A)[2]), "r"((A)[3]), "r"(B0), "r"(B1))
#define BSYNC(id)   asm volatile("bar.sync %0, %1;"   :: "r"(id), "r"(THREADS) : "memory")
#define BARRIVE(id) asm volatile("bar.arrive %0, %1;" :: "r"(id), "r"(THREADS) : "memory")

// fast-math-proof sincos: double range reduction + fdlibm float polys
__device__ __forceinline__ void sincos_pos(float x, float& s, float& c) {
    float nf = rintf(x * 0.63661977236758134f);
    float rf = (float)((double)x - (double)nf * 1.5707963267948966);
    int q = (int)nf;
    float r2 = rf * rf;
    float ps = fmaf(r2, 2.7557314297e-06f, -1.9841271110e-04f);
    ps = fmaf(r2, ps, 8.3333337680e-03f);
    ps = fmaf(r2, ps, -1.6666667163e-01f);
    float sr = fmaf(rf * r2, ps, rf);
    float pc = fmaf(r2, 2.4760174663e-05f, -1.3888889225e-03f);
    pc = fmaf(r2, pc, 4.1666667908e-02f);
    pc = fmaf(r2, pc, -0.5f);
    float cr = fmaf(r2, pc, 1.0f);
    if (q & 1) { float t = sr; sr = cr; cr = -t; }
    if (q & 2) { sr = -sr; cr = -cr; }
    s = sr; c = cr;
}

__device__ __forceinline__ void relu_pack(float acc[16][4], uint32_t a[8][4]) {
#pragma unroll
    for (int n = 0; n < 16; ++n)
#pragma unroll
        for (int j = 0; j < 4; ++j) { float v = acc[n][j]; acc[n][j] = fmaxf(v, 0.01f * v); }
#pragma unroll
    for (int j = 0; j < 8; ++j) {
        a[j][0] = packh2(acc[2*j][0],   acc[2*j][1]);
        a[j][1] = packh2(acc[2*j][2],   acc[2*j][3]);
        a[j][2] = packh2(acc[2*j+1][0], acc[2*j+1][1]);
        a[j][3] = packh2(acc[2*j+1][2], acc[2*j+1][3]);
    }
}

__device__ __forceinline__ void layer_hidden(uint32_t wl, const float* bl, int lane, uint32_t a[8][4]) {
    float acc[16][4];
    const int c0 = 2 * (lane & 3);
#pragma unroll
    for (int n = 0; n < 16; ++n) {
        float2 bv = *(const float2*)(bl + n * 8 + c0);
        acc[n][0] = bv.x; acc[n][1] = bv.y; acc[n][2] = bv.x; acc[n][3] = bv.y;
    }
#pragma unroll
    for (int k = 0; k < 8; ++k)
#pragma unroll
        for (int n2 = 0; n2 < 8; ++n2) {
            uint32_t B[4];
            LDSM_X4_T(B, wl + (uint32_t)(k * 16 * WSTRIDE + n2 * 16) * 2u);
            MMA(acc[2*n2],   a[k], B[0], B[1]);
            MMA(acc[2*n2+1], a[k], B[2], B[3]);
        }
    relu_pack(acc, a);
}

__global__ void __launch_bounds__(THREADS, 1)
fused_mlp(const float* __restrict__ UV, const float* __restrict__ FG,
          const float* __restrict__ W0, const float* __restrict__ b0,
          const float* __restrict__ W1, const float* __restrict__ b1,
          const float* __restrict__ W2, const float* __restrict__ b2,
          const float* __restrict__ W3, const float* __restrict__ b3,
          const float* __restrict__ W4, const float* __restrict__ b4,
          float* __restrict__ out)
{
    extern __shared__ char sm[];
    __half* sW0 = (__half*)(sm + OFF_W0);
    float*  sB  = (float*)(sm + OFF_B);
    float*  sB4 = (float*)(sm + OFF_B4);
    char*   sX  = sm + OFF_X;
    const int tid = threadIdx.x, lane = tid & 31, wid = tid >> 5;

    // one-time staging: W0 rows permuted (0-99: feat rows 66-165; 104-169: posenc rows 0-65)
    for (int i = tid; i < 176 * 128; i += THREADS) {
        int k = i >> 7, n = i & 127;
        float v = 0.0f;
        if (k < 100) v = W0[(66 + k) * 128 + n];
        else if (k >= 104 && k < 170) v = W0[(k - 104) * 128 + n];
        sW0[k * WSTRIDE + n] = __float2half_rn(v);
    }
    for (int i = tid; i < 128 * 128; i += THREADS) {
        int k = i >> 7, n = i & 127;
        ((__half*)(sm + OFF_W1))[k * WSTRIDE + n] = __float2half_rn(W1[i]);
        ((__half*)(sm + OFF_W2))[k * WSTRIDE + n] = __float2half_rn(W2[i]);
        ((__half*)(sm + OFF_W3))[k * WSTRIDE + n] = __float2half_rn(W3[i]);
    }
    for (int i = tid; i < 128 * 8; i += THREADS)
        ((__half*)(sm + OFF_W4))[i] = __float2half_rn((i & 7) < 3 ? W4[(i >> 3) * 3 + (i & 7)] : 0.0f);
    for (int i = tid; i < 128; i += THREADS) {
        sB[i] = b0[i]; sB[128 + i] = b1[i]; sB[256 + i] = b2[i]; sB[384 + i] = b3[i];
    }
    if (tid < 8) sB4[tid] = (tid < 3) ? b4[tid] : 0.0f;
    for (int i = tid; i < 128 * XSTRIDE / 4; i += THREADS) ((uint32_t*)sX)[i] = 0u;
    __syncthreads();

    const uint32_t wlp = (uint32_t)((lane & 15) * WSTRIDE + ((lane >> 4) << 3)) * 2u;

    if (wid >= 8) {  // ---------- producers: gather + posenc ----------
        const int row_base = (wid - 8) * 32;
        const float2* UV2 = (const float2*)UV;
        const float4* FG4 = (const float4*)FG;
        bool first = true;
        for (int t = blockIdx.x; t < NTILES; t += gridDim.x) {
            if (!first) BSYNC(2);
            first = false;
            const int myrow = row_base + lane;
            float2 uvp = UV2[t * 128 + myrow];
            float iU = 511.0f * uvp.x, iV = 511.0f * uvp.y;
            int iu0 = (int)floorf(iU), iu1 = (int)ceilf(iU);
            int iv0 = (int)floorf(iV), iv1 = (int)ceilf(iV);
            float fu = iU - (float)iu0, fv = iV - (float)iv0;
            int b00 = (iu0 * 512 + iv0) * 25, b10 = (iu1 * 512 + iv0) * 25;
            int b01 = (iu0 * 512 + iv1) * 25, b11 = (iu1 * 512 + iv1) * 25;
            float w00 = (1.f - fu) * (1.f - fv), w10 = fu * (1.f - fv);
            float w01 = (1.f - fu) * fv, w11 = fu * fv;
            float4 q[4][4];
#pragma unroll
            for (int s = 0; s < 4; ++s) {
                int c00 = __shfl_sync(~0u, b00, s), c10 = __shfl_sync(~0u, b10, s);
                int c01 = __shfl_sync(~0u, b01, s), c11 = __shfl_sync(~0u, b11, s);
                if (lane < 25) {
                    q[s][0] = FG4[c00 + lane]; q[s][1] = FG4[c10 + lane];
                    q[s][2] = FG4[c01 + lane]; q[s][3] = FG4[c11 + lane];
                }
            }
#pragma unroll 4
            for (int p = 0; p < 32; ++p) {
                const int s = p & 3;
                float u00 = __shfl_sync(~0u, w00, p), u10 = __shfl_sync(~0u, w10, p);
                float u01 = __shfl_sync(~0u, w01, p), u11 = __shfl_sync(~0u, w11, p);
                if (lane < 25) {
                    float4 f;
                    f.x = q[s][0].x*u00 + q[s][1].x*u10 + q[s][2].x*u01 + q[s][3].x*u11;
                    f.y = q[s][0].y*u00 + q[s][1].y*u10 + q[s][2].y*u01 + q[s][3].y*u11;
                    f.z = q[s][0].z*u00 + q[s][1].z*u10 + q[s][2].z*u01 + q[s][3].z*u11;
                    f.w = q[s][0].w*u00 + q[s][1].w*u10 + q[s][2].w*u01 + q[s][3].w*u11;
                    uint2 st; st.x = packh2(f.x, f.y); st.y = packh2(f.z, f.w);
                    *(uint2*)(sX + (row_base + p) * XSTRIDE + lane * 8) = st;
                }
                const int np = p + 4;
                if (np < 32) {
                    int c00 = __shfl_sync(~0u, b00, np), c10 = __shfl_sync(~0u, b10, np);
                    int c01 = __shfl_sync(~0u, b01, np), c11 = __shfl_sync(~0u, b11, np);
                    if (lane < 25) {
                        q[s][0] = FG4[c00 + lane]; q[s][1] = FG4[c10 + lane];
                        q[s][2] = FG4[c01 + lane]; q[s][3] = FG4[c11 + lane];
                    }
                }
            }
            {   // posenc: cols 104..169 (order U,V, sU,sV, cU,cV, ...)
                char* dst = sX + myrow * XSTRIDE + 208;
                *(uint32_t*)dst = packh2(uvp.x, uvp.y);
                float kf = 1.0f;
                for (int i = 0; i < 16; ++i) {
                    float su, cu, sv, cv;
                    sincos_pos(kf * uvp.x, su, cu);
                    sincos_pos(kf * uvp.y, sv, cv);
                    *(uint32_t*)(dst + 4 + 8 * i) = packh2(su, sv);
                    *(uint32_t*)(dst + 8 + 8 * i) = packh2(cu, cv);
                    kf *= 2.0f;
                }
            }
            asm volatile("membar.cta;" ::: "memory");
            BARRIVE(1);
        }
    } else {  // ---------- consumers: 5-layer MLP, register-chained ----------
        const int m0 = wid * 16;
        const uint32_t xs = s2u(sX) + (uint32_t)((m0 + (lane & 15)) * XSTRIDE + ((lane >> 4) << 4));
        const int c0 = 2 * (lane & 3);
        for (int t = blockIdx.x; t < NTILES; t += gridDim.x) {
            BSYNC(1);
            // layer 0: STREAM A fragments (distance-1 prefetch, double-buffered)
            // instead of preloading a0[11][4] -- kills the register spills.
            float acc[16][4];
#pragma unroll
            for (int n = 0; n < 16; ++n) {
                float2 bv = *(const float2*)(sB + n * 8 + c0);
                acc[n][0] = bv.x; acc[n][1] = bv.y; acc[n][2] = bv.x; acc[n][3] = bv.y;
            }
            const uint32_t w0l = s2u(sm + OFF_W0) + wlp;
            uint32_t af[2][4];
            LDSM_X4(af[0], xs);
#pragma unroll
            for (int k = 0; k < 11; ++k) {
                if (k < 10) LDSM_X4(af[(k + 1) & 1], xs + (uint32_t)((k + 1) * 32));
#pragma unroll
                for (int n2 = 0; n2 < 8; ++n2) {
                    uint32_t B[4];
                    LDSM_X4_T(B, w0l + (uint32_t)(k * 16 * WSTRIDE + n2 * 16) * 2u);
                    MMA(acc[2*n2],   af[k & 1], B[0], B[1]);
                    MMA(acc[2*n2+1], af[k & 1], B[2], B[3]);
                }
            }
            BARRIVE(2);  // X fully consumed -> producers refill
            uint32_t a[8][4];
            relu_pack(acc, a);
            layer_hidden(s2u(sm + OFF_W1) + wlp, sB + 128, lane, a);
            layer_hidden(s2u(sm + OFF_W2) + wlp, sB + 256, lane, a);
            layer_hidden(s2u(sm + OFF_W3) + wlp, sB + 384, lane, a);
            float c4[4];
            c4[0] = sB4[c0]; c4[1] = sB4[c0 + 1]; c4[2] = c4[0]; c4[3] = c4[1];
            const uint32_t w4l = s2u(sm + OFF_W4) + (uint32_t)((lane & 15) * 16);
#pragma unroll
            for (int k = 0; k < 8; ++k) {
                uint32_t B[2];
                LDSM_X2_T(B, w4l + (uint32_t)(k * 256));
                MMA(c4, a[k], B[0], B[1]);
            }
            const int pt = t * 128 + m0 + (lane >> 2);
            if ((lane & 3) == 0) {
                out[pt * 3 + 0] = c4[0];       out[pt * 3 + 1] = c4[1];
                out[(pt + 8) * 3 + 0] = c4[2]; out[(pt + 8) * 3 + 1] = c4[3];
            } else if ((lane & 3) == 1) {
                out[pt * 3 + 2] = c4[0];
                out[(pt + 8) * 3 + 2] = c4[2];
            }
        }
    }
}

extern "C" void kernel_launch(void* const* d_in, const int* in_sizes, int n_in,
                              void* d_out, int out_size) {
    int dev = 0, sms = 148;
    cudaGetDevice(&dev);
    cudaDeviceGetAttribute(&sms, cudaDevAttrMultiProcessorCount, dev);
    if (sms <= 0) sms = 148;
    if (sms > NTILES) sms = NTILES;
    cudaFuncSetAttribute(fused_mlp, cudaFuncAttributeMaxDynamicSharedMemorySize, SMEM_TOTAL);
    fused_mlp<<<sms, THREADS, SMEM_TOTAL>>>(
        (const float*)d_in[0], (const float*)d_in[1],
        (const float*)d_in[2], (const float*)d_in[3],
        (const float*)d_in[4], (const float*)d_in[5],
        (const float*)d_in[6], (const float*)d_in[7],
        (const float*)d_in[8], (const float*)d_in[9],
        (const float*)d_in[10], (const float*)d_in[11],
        (float*)d_out);
}